// round 2
// baseline (speedup 1.0000x reference)
#include <cuda_runtime.h>

#define BB 4
#define SS 2048
#define DD 16
#define HH 16
#define BH (BB*HH)          // 64 (b,h) pairs
#define QT 64               // queries per half-tile
#define NT (SS/QT)          // 32 tiles per head
#define ATTN_THREADS 128    // 2 half-tiles per block

// Scratch (device globals: no allocation in kernel_launch)
__device__ float g_Q[BH*SS];
__device__ float g_K[BH*SS];
__device__ float g_V[BH*SS];
__device__ float g_att[BB*SS*DD];   // [b][s][h] row-major

// ---------------------------------------------------------------------------
// Pass 1: qkv = x @ w_qkv + b_qkv, scatter to head-major Q/K/V
// ---------------------------------------------------------------------------
__global__ __launch_bounds__(256) void qkv_kernel(const float* __restrict__ x,
                                                  const float* __restrict__ w,
                                                  const float* __restrict__ bias) {
    __shared__ float sw[16*48];
    __shared__ float sb[48];
    int tid = threadIdx.x;
    for (int i = tid; i < 16*48; i += 256) sw[i] = w[i];
    if (tid < 48) sb[tid] = bias[tid];
    __syncthreads();

    int row = blockIdx.x * 256 + tid;          // 0..8191  (b*2048 + s)
    float xr[16];
    const float4* xp = (const float4*)(x + row * 16);
    #pragma unroll
    for (int i = 0; i < 4; i++) {
        float4 v = xp[i];
        xr[4*i+0] = v.x; xr[4*i+1] = v.y; xr[4*i+2] = v.z; xr[4*i+3] = v.w;
    }
    int b = row >> 11;
    int s = row & (SS - 1);

    float o[48];
    #pragma unroll
    for (int c = 0; c < 48; c++) {
        float acc = sb[c];
        #pragma unroll
        for (int k = 0; k < 16; k++) acc = fmaf(xr[k], sw[k*48 + c], acc);
        o[c] = acc;
    }
    #pragma unroll
    for (int h = 0; h < 16; h++) {
        int base = (b*16 + h) * SS + s;        // coalesced across warp (s contiguous)
        g_Q[base] = o[h];
        g_K[base] = o[16 + h];
        g_V[base] = o[32 + h];
    }
}

// ---------------------------------------------------------------------------
// Pass 2: per-(b,h) scalar-head causal softmax-weighted sum.
// Block = (head, half-tile pair {t, NT-1-t}) -> exactly equal work per block.
// 1024 equal blocks -> per-SM MUFU-work imbalance ~1.2% (vs 15.6% at 512).
// k,v interleaved in SMEM; inner loop is warp-uniform broadcast LDS.
// Row max via sign(q)*block{max,min}(k): no online softmax needed.
// ---------------------------------------------------------------------------
__global__ __launch_bounds__(ATTN_THREADS) void attn_kernel() {
    __shared__ float2 skv[SS];
    __shared__ float red_mx[ATTN_THREADS/32], red_mn[ATTN_THREADS/32];

    int bh  = blockIdx.y;                  // 0..63
    int t   = blockIdx.x;                  // 0..NT/2-1
    int t2  = NT - 1 - t;                  // mirror tile
    int jend = (t2 + 1) * QT;              // covers both tiles' causal range
    int tid = threadIdx.x;

    const float* __restrict__ Kp = g_K + bh * SS;
    const float* __restrict__ Vp = g_V + bh * SS;

    float mx = -3.4e38f, mn = 3.4e38f;
    for (int j = tid; j < jend; j += ATTN_THREADS) {
        float kj = Kp[j], vj = Vp[j];
        skv[j] = make_float2(kj, vj);
        mx = fmaxf(mx, kj);
        mn = fminf(mn, kj);
    }
    #pragma unroll
    for (int o = 16; o > 0; o >>= 1) {
        mx = fmaxf(mx, __shfl_xor_sync(0xFFFFFFFFu, mx, o));
        mn = fminf(mn, __shfl_xor_sync(0xFFFFFFFFu, mn, o));
    }
    if ((tid & 31) == 0) { red_mx[tid >> 5] = mx; red_mn[tid >> 5] = mn; }
    __syncthreads();
    mx = red_mx[0]; mn = red_mn[0];
    #pragma unroll
    for (int i = 1; i < ATTN_THREADS/32; i++) {
        mx = fmaxf(mx, red_mx[i]);
        mn = fminf(mn, red_mn[i]);
    }

    // thread -> query: first QT threads take tile t, rest take mirror tile t2
    int q = (tid < QT) ? (t * QT + tid) : (t2 * QT + (tid - QT));

    float qv = g_Q[bh * SS + q];
    const float L2E = 1.4426950408889634f;
    float qc  = qv * L2E;
    float nmc = -qc * ((qv >= 0.f) ? mx : mn);   // -log2-domain row-max bound (>= prefix max)

    float num = 0.f, den = 0.f;
    #pragma unroll 4
    for (int j = 0; j <= q; j++) {
        float2 kv = skv[j];                       // warp-uniform broadcast
        float a = fmaf(qc, kv.x, nmc);            // <= 0 always
        float e;
        asm("ex2.approx.ftz.f32 %0, %1;" : "=f"(e) : "f"(a));
        num = fmaf(e, kv.y, num);
        den += e;
    }
    float out = num / den;

    int b = bh >> 4, h = bh & 15;
    g_att[(b * SS + q) * DD + h] = out;
}

// ---------------------------------------------------------------------------
// Pass 3: y = att @ w_out + b_out
// ---------------------------------------------------------------------------
__global__ __launch_bounds__(256) void out_kernel(const float* __restrict__ w,
                                                  const float* __restrict__ bias,
                                                  float* __restrict__ out) {
    __shared__ float sw[16*16];
    __shared__ float sb[16];
    int tid = threadIdx.x;
    if (tid < 256) sw[tid] = w[tid];
    if (tid < 16)  sb[tid] = bias[tid];
    __syncthreads();

    int row = blockIdx.x * 256 + tid;           // 0..8191
    float xr[16];
    const float4* xp = (const float4*)(g_att + row * 16);
    #pragma unroll
    for (int i = 0; i < 4; i++) {
        float4 v = xp[i];
        xr[4*i+0] = v.x; xr[4*i+1] = v.y; xr[4*i+2] = v.z; xr[4*i+3] = v.w;
    }
    float o[16];
    #pragma unroll
    for (int c = 0; c < 16; c++) {
        float acc = sb[c];
        #pragma unroll
        for (int k = 0; k < 16; k++) acc = fmaf(xr[k], sw[k*16 + c], acc);
        o[c] = acc;
    }
    float4* op = (float4*)(out + row * 16);
    #pragma unroll
    for (int i = 0; i < 4; i++)
        op[i] = make_float4(o[4*i+0], o[4*i+1], o[4*i+2], o[4*i+3]);
}

// ---------------------------------------------------------------------------
extern "C" void kernel_launch(void* const* d_in, const int* in_sizes, int n_in,
                              void* d_out, int out_size) {
    const float* x     = (const float*)d_in[0];
    const float* w_qkv = (const float*)d_in[1];
    const float* b_qkv = (const float*)d_in[2];
    const float* w_out = (const float*)d_in[3];
    const float* b_out = (const float*)d_in[4];
    float* y = (float*)d_out;

    qkv_kernel<<<(BB*SS)/256, 256>>>(x, w_qkv, b_qkv);
    attn_kernel<<<dim3(NT/2, BH), ATTN_THREADS>>>();
    out_kernel<<<(BB*SS)/256, 256>>>(w_out, b_out, y);
}

// round 4
// speedup vs baseline: 1.0045x; 1.0045x over previous
#include <cuda_runtime.h>
#include <cstdint>

#define BB 4
#define SS 2048
#define DD 16
#define HH 16
#define BH (BB*HH)          // 64 (b,h) pairs
#define QT 64               // queries per half-tile
#define NT (SS/QT)          // 32 tiles per head
#define ATTN_THREADS 128    // 2 half-tiles per block

// Scratch (device globals: no allocation in kernel_launch)
__device__ float g_Q[BH*SS];
__device__ float g_K[BH*SS];
__device__ float g_V[BH*SS];
__device__ float g_att[BB*SS*DD];   // [b][s][h] row-major

// ---------------- packed f32x2 helpers (sm_100+) ----------------
__device__ __forceinline__ uint64_t pk2(float lo, float hi) {
    uint64_t r; asm("mov.b64 %0, {%1,%2};" : "=l"(r) : "f"(lo), "f"(hi)); return r;
}
__device__ __forceinline__ void upk2(uint64_t p, float& lo, float& hi) {
    asm("mov.b64 {%0,%1}, %2;" : "=f"(lo), "=f"(hi) : "l"(p));
}
__device__ __forceinline__ uint64_t fma2_(uint64_t a, uint64_t b, uint64_t c) {
    uint64_t d; asm("fma.rn.f32x2 %0, %1, %2, %3;" : "=l"(d) : "l"(a), "l"(b), "l"(c)); return d;
}
__device__ __forceinline__ uint64_t add2_(uint64_t a, uint64_t b) {
    uint64_t d; asm("add.rn.f32x2 %0, %1, %2;" : "=l"(d) : "l"(a), "l"(b)); return d;
}
__device__ __forceinline__ float ex2f(float a) {
    float e; asm("ex2.approx.ftz.f32 %0, %1;" : "=f"(e) : "f"(a)); return e;
}

// ---------------------------------------------------------------------------
// Pass 1: qkv = x @ w_qkv + b_qkv, scatter to head-major Q/K/V.
// 3-way column split -> 96 blocks (was 32) to cover the chip.
// ---------------------------------------------------------------------------
__global__ __launch_bounds__(256) void qkv_kernel(const float* __restrict__ x,
                                                  const float* __restrict__ w,
                                                  const float* __restrict__ bias) {
    __shared__ float sw[16*48];
    __shared__ float sb[48];
    int tid = threadIdx.x;
    for (int i = tid; i < 16*48; i += 256) sw[i] = w[i];
    if (tid < 48) sb[tid] = bias[tid];
    __syncthreads();

    int gid = blockIdx.x * 256 + tid;          // 0..24575
    int sec = gid >> 13;                       // 0,1,2 (warp-uniform: 8192 % 32 == 0)
    int row = gid & 8191;                      // b*2048 + s

    float xr[16];
    const float4* xp = (const float4*)(x + row * 16);
    #pragma unroll
    for (int i = 0; i < 4; i++) {
        float4 v = xp[i];
        xr[4*i+0] = v.x; xr[4*i+1] = v.y; xr[4*i+2] = v.z; xr[4*i+3] = v.w;
    }
    int b = row >> 11;
    int s = row & (SS - 1);
    int cbase = sec * 16;

    float o[16];
    #pragma unroll
    for (int c = 0; c < 16; c++) {
        float acc = sb[cbase + c];
        #pragma unroll
        for (int k = 0; k < 16; k++) acc = fmaf(xr[k], sw[k*48 + cbase + c], acc);
        o[c] = acc;
    }
    float* dst = (sec == 0) ? g_Q : (sec == 1) ? g_K : g_V;
    #pragma unroll
    for (int h = 0; h < 16; h++) {
        dst[(b*16 + h) * SS + s] = o[h];       // coalesced across warp (s contiguous)
    }
}

// ---------------------------------------------------------------------------
// Pass 2: per-(b,h) scalar-head causal softmax-weighted sum.
// Block = (head, half-tile pair {t, NT-1-t}) -> exactly equal work per block.
// Inner loop: f32x2-packed fma work; exps split 3:1 MUFU : fma-pipe poly
// (magic-round range reduction + deg-4 2^f Taylor + int exponent splice)
// to lift the MUFU rt=8 bound to a ~6 cyc/elem multi-pipe bound.
// ---------------------------------------------------------------------------
__global__ __launch_bounds__(ATTN_THREADS) void attn_kernel() {
    __shared__ __align__(16) float sK[SS];     // 16B align: LDS.64/STS.128 views
    __shared__ __align__(16) float sV[SS];
    __shared__ float red_mx[ATTN_THREADS/32], red_mn[ATTN_THREADS/32];

    int bh  = blockIdx.y;                  // 0..63
    int t   = blockIdx.x;                  // 0..NT/2-1
    int t2  = NT - 1 - t;                  // mirror tile
    int jend = (t2 + 1) * QT;              // covers both tiles' causal range
    int tid = threadIdx.x;

    const float* __restrict__ Kp = g_K + bh * SS;
    const float* __restrict__ Vp = g_V + bh * SS;

    float mx = -3.4e38f, mn = 3.4e38f;
    for (int j = tid * 4; j < jend; j += ATTN_THREADS * 4) {
        float4 k4 = *(const float4*)(Kp + j);
        float4 v4 = *(const float4*)(Vp + j);
        *(float4*)(sK + j) = k4;
        *(float4*)(sV + j) = v4;
        mx = fmaxf(mx, fmaxf(fmaxf(k4.x, k4.y), fmaxf(k4.z, k4.w)));
        mn = fminf(mn, fminf(fminf(k4.x, k4.y), fminf(k4.z, k4.w)));
    }
    #pragma unroll
    for (int o = 16; o > 0; o >>= 1) {
        mx = fmaxf(mx, __shfl_xor_sync(0xFFFFFFFFu, mx, o));
        mn = fminf(mn, __shfl_xor_sync(0xFFFFFFFFu, mn, o));
    }
    if ((tid & 31) == 0) { red_mx[tid >> 5] = mx; red_mn[tid >> 5] = mn; }
    __syncthreads();
    mx = red_mx[0]; mn = red_mn[0];
    #pragma unroll
    for (int i = 1; i < ATTN_THREADS/32; i++) {
        mx = fmaxf(mx, red_mx[i]);
        mn = fminf(mn, red_mn[i]);
    }

    // thread -> query: first QT threads take tile t, rest take mirror tile t2
    int q = (tid < QT) ? (t * QT + tid) : (t2 * QT + (tid - QT));

    float qv = g_Q[bh * SS + q];
    const float L2E = 1.4426950408889634f;
    float qc  = qv * L2E;
    float nmc = -qc * ((qv >= 0.f) ? mx : mn);   // -log2-domain row-max bound (>= prefix max)

    const uint64_t qc2  = pk2(qc, qc);
    const uint64_t nmc2 = pk2(nmc, nmc);
    const float MAGIC = 12582912.0f;             // 1.5 * 2^23 (round-to-nearest trick)
    const uint64_t MAGIC2  = pk2(MAGIC, MAGIC);
    const uint64_t NMAGIC2 = pk2(-MAGIC, -MAGIC);
    const uint64_t NEG1_2  = pk2(-1.0f, -1.0f);
    // 2^f Taylor, f in [-0.5, 0.5]; rel err ~4e-5
    const uint64_t C4_2 = pk2(0.00961813f, 0.00961813f);
    const uint64_t C3_2 = pk2(0.05550411f, 0.05550411f);
    const uint64_t C2_2 = pk2(0.24022651f, 0.24022651f);
    const uint64_t C1_2 = pk2(0.69314718f, 0.69314718f);
    const uint64_t C0_2 = pk2(1.0f, 1.0f);

    const uint64_t* sK64 = (const uint64_t*)sK;
    const uint64_t* sV64 = (const uint64_t*)sV;

    uint64_t num2 = 0, den2 = 0;                 // pk2(0,0) == 0

// pair (j, j+1), MUFU exp
#define PAIR_M(i) { \
    uint64_t kk = sK64[(i) >> 1], vv = sV64[(i) >> 1]; \
    uint64_t a2 = fma2_(qc2, kk, nmc2); \
    float al, ah; upk2(a2, al, ah); \
    uint64_t ee = pk2(ex2f(al), ex2f(ah)); \
    num2 = fma2_(ee, vv, num2); \
    den2 = add2_(den2, ee); }

// pair (j, j+1), fma-pipe polynomial exp2 (offloads MUFU)
#define PAIR_P(i) { \
    uint64_t kk = sK64[(i) >> 1], vv = sV64[(i) >> 1]; \
    uint64_t a2  = fma2_(qc2, kk, nmc2); \
    uint64_t t2_ = add2_(a2, MAGIC2); \
    uint64_t nf2 = add2_(t2_, NMAGIC2); \
    uint64_t f2  = fma2_(nf2, NEG1_2, a2); \
    uint64_t p2  = fma2_(f2, C4_2, C3_2); \
    p2 = fma2_(f2, p2, C2_2); \
    p2 = fma2_(f2, p2, C1_2); \
    p2 = fma2_(f2, p2, C0_2); \
    float tl, th, pl, ph; upk2(t2_, tl, th); upk2(p2, pl, ph); \
    int el = __float_as_int(pl) + (__float_as_int(tl) << 23); \
    int eh = __float_as_int(ph) + (__float_as_int(th) << 23); \
    uint64_t ee = pk2(__int_as_float(el), __int_as_float(eh)); \
    num2 = fma2_(ee, vv, num2); \
    den2 = add2_(den2, ee); }

    int n = q + 1;
    int i = 0;
    for (; i + 8 <= n; i += 8) {
        PAIR_M(i); PAIR_M(i + 2); PAIR_M(i + 4); PAIR_P(i + 6);
    }
    for (; i + 2 <= n; i += 2) { PAIR_M(i); }

    float nlo, nhi, dlo, dhi;
    upk2(num2, nlo, nhi); upk2(den2, dlo, dhi);
    float num = nlo + nhi, den = dlo + dhi;
    if (i < n) {   // odd remainder element
        float a = fmaf(qc, sK[i], nmc);
        float e = ex2f(a);
        num = fmaf(e, sV[i], num);
        den += e;
    }
    float out = num / den;

    int b = bh >> 4, h = bh & 15;
    g_att[(b * SS + q) * DD + h] = out;
#undef PAIR_M
#undef PAIR_P
}

// ---------------------------------------------------------------------------
// Pass 3: y = att @ w_out + b_out. 4-way column split -> 128 blocks.
// ---------------------------------------------------------------------------
__global__ __launch_bounds__(256) void out_kernel(const float* __restrict__ w,
                                                  const float* __restrict__ bias,
                                                  float* __restrict__ out) {
    __shared__ float sw[16*16];
    __shared__ float sb[16];
    int tid = threadIdx.x;
    if (tid < 256) sw[tid] = w[tid];
    if (tid < 16)  sb[tid] = bias[tid];
    __syncthreads();

    int gid = blockIdx.x * 256 + tid;           // 0..32767
    int row = gid >> 2;                          // 0..8191
    int seg = gid & 3;                           // 4 output cols each

    float xr[16];
    const float4* xp = (const float4*)(g_att + row * 16);
    #pragma unroll
    for (int i = 0; i < 4; i++) {
        float4 v = xp[i];
        xr[4*i+0] = v.x; xr[4*i+1] = v.y; xr[4*i+2] = v.z; xr[4*i+3] = v.w;
    }
    float o[4];
    #pragma unroll
    for (int cc = 0; cc < 4; cc++) {
        int c = seg * 4 + cc;
        float acc = sb[c];
        #pragma unroll
        for (int k = 0; k < 16; k++) acc = fmaf(xr[k], sw[k*16 + c], acc);
        o[cc] = acc;
    }
    *(float4*)(out + row * 16 + seg * 4) = make_float4(o[0], o[1], o[2], o[3]);
}

// ---------------------------------------------------------------------------
extern "C" void kernel_launch(void* const* d_in, const int* in_sizes, int n_in,
                              void* d_out, int out_size) {
    const float* x     = (const float*)d_in[0];
    const float* w_qkv = (const float*)d_in[1];
    const float* b_qkv = (const float*)d_in[2];
    const float* w_out = (const float*)d_in[3];
    const float* b_out = (const float*)d_in[4];
    float* y = (float*)d_out;

    qkv_kernel<<<(3*BB*SS)/256, 256>>>(x, w_qkv, b_qkv);
    attn_kernel<<<dim3(NT/2, BH), ATTN_THREADS>>>();
    out_kernel<<<(4*BB*SS)/256, 256>>>(w_out, b_out, y);
}